// round 9
// baseline (speedup 1.0000x reference)
#include <cuda_runtime.h>
#include <cuda_fp16.h>
#include <cstdint>

// LorentzConv1d via single-pass fp16 mma.sync m16n8k16 (fp32 accum).
// Warp tile 32x64, 16 warps, MT=512 rows/CTA, grid=256. Warp-private A staging.
//
// Round 9 K-permutation (K=384, 24 kb x 8 slots), adjacency-preserving:
//   kb = 3*cg + kkIdx, kk = 2*kkIdx in {0,2,4}, cg in 0..7
//   slot s4   = taps (kk, kk+1) of channel c0   = 8cg + 2s4
//   slot s4+4 = taps (kk, kk+1) of channel c0+1
//   c0=0 (time) and tap 5 multiply B=0.
// A fragment {a0,a2} = LDS.64 at xp[(q4+kk)*XPS + c0]; {a1,a3} at row +8.
// xp[r][c] = {h(x[g+r,c]), h(x[g+r+1,c])}, g = l0 + wid*32 - 2, XPS=72
// -> 8B-unit bank = 4*q4 + s4 + const: conflict-free both phases.

#define LLEN 8192
#define CIN  64
#define MT   512
#define XPS  72
#define WPRIV (36 * XPS)              // 2592 words per warp
#define WB4_OFF (16 * WPRIV)          // 41472 (16B aligned)
#define B_OFF   (WB4_OFF + 128)       // 41600 (16B aligned)
#define LGSTR   97                    // uint4 units per lane slot (24*4 + 1, odd)
#define B_UNITS (32 * LGSTR)          // 3104
#define SMEM_WORDS (B_OFF + B_UNITS * 4)  // 54016
#define SMEM_BYTES (SMEM_WORDS * 4)       // 216064

__device__ __forceinline__ uint32_t h2pack(float a, float b) {
    __half2 h = __floats2half2_rn(a, b);
    return *(uint32_t*)&h;
}
__device__ __forceinline__ void mma_f16(float* d, uint32_t a0, uint32_t a1,
                                        uint32_t a2, uint32_t a3,
                                        uint32_t b0, uint32_t b1) {
    asm volatile(
        "mma.sync.aligned.m16n8k16.row.col.f32.f16.f16.f32 "
        "{%0,%1,%2,%3}, {%4,%5,%6,%7}, {%8,%9}, {%0,%1,%2,%3};"
        : "+f"(d[0]), "+f"(d[1]), "+f"(d[2]), "+f"(d[3])
        : "r"(a0), "r"(a1), "r"(a2), "r"(a3), "r"(b0), "r"(b1));
}
// W weight for (kb, slot s4h, elem t): channel ch, tap kk+t
__device__ __forceinline__ float slotW(const float* __restrict__ W, int n,
                                       int kb, int s4h, int t) {
    int kk = 2 * (kb % 3);
    int cg = kb / 3;
    int ch = 8 * cg + 2 * (s4h & 3) + (s4h >> 2);
    int tap = kk + t;
    if (ch < 1 || tap > 4) return 0.f;
    return W[(size_t)n * 316 + (ch - 1) * 5 + tap + 1];
}
__device__ __forceinline__ float tresc(const float* __restrict__ xb, int l) {
    float s = -4.0f;
#pragma unroll
    for (int k = 0; k < 5; k++) {
        int g = l - 2 + k;
        float t = ((unsigned)g < (unsigned)LLEN) ? xb[(size_t)g * CIN] : 1.0f;
        s = fmaf(t, t, s);
    }
    return sqrtf(s);
}

__global__ __launch_bounds__(512, 1)
void lorentz_f16_kernel(const float* __restrict__ x,
                        const float* __restrict__ W,
                        const float* __restrict__ bvec,
                        float* __restrict__ out)
{
    extern __shared__ uint32_t sm[];
    float4* wb4 = (float4*)(sm + WB4_OFF);
    uint4*  BQ4 = (uint4*)(sm + B_OFF);

    const int tid  = threadIdx.x;
    const int wid  = tid >> 5;
    const int lane = tid & 31;
    const int bidx = blockIdx.x >> 4;          // 16 tiles per batch
    const int l0   = (blockIdx.x & 15) << 9;   // 512 rows per tile
    const float* xb = x + (size_t)bidx * (LLEN * CIN);

    // ---- stage B (CTA-shared): unit (lg, kb, i) holds n = 16i+q4g and 16i+8+q4g ----
    for (int u = tid; u < 32 * 24 * 4; u += 512) {
        int i  = u & 3;
        int t2 = u >> 2;
        int kb = t2 % 24;
        int lg = t2 / 24;                      // 0..31
        int q4g = lg >> 2, s4g = lg & 3;
        int n0 = 16 * i + q4g;
        int n1 = n0 + 8;
        uint4 w;
        w.x = h2pack(slotW(W, n0, kb, s4g, 0),     slotW(W, n0, kb, s4g, 1));
        w.y = h2pack(slotW(W, n0, kb, s4g + 4, 0), slotW(W, n0, kb, s4g + 4, 1));
        w.z = h2pack(slotW(W, n1, kb, s4g, 0),     slotW(W, n1, kb, s4g, 1));
        w.w = h2pack(slotW(W, n1, kb, s4g + 4, 0), slotW(W, n1, kb, s4g + 4, 1));
        BQ4[lg * LGSTR + kb * 4 + i] = w;
    }
    // ---- fp32 time-weight + bias pairs ----
    if (tid < 32) {
        wb4[tid] = make_float4(W[(size_t)(2 * tid) * 316], bvec[2 * tid],
                               W[(size_t)(2 * tid + 1) * 316], bvec[2 * tid + 1]);
    }
    __syncthreads();   // the ONLY CTA-wide barrier

    // ---- warp-private xp staging: 36 row-pairs, xp[r][c] = {x[g+r,c], x[g+r+1,c]} ----
    const int wrow   = wid * 32;
    const int wpbase = wid * WPRIV;
    {
        const int gbase = l0 + wrow - 2;
#pragma unroll
        for (int j = 0; j < 18; j++) {
            int u  = j * 32 + lane;
            int r  = u >> 4, c4 = u & 15;
            int g  = gbase + r;
            float4 v0, v1;
            if ((unsigned)g < (unsigned)LLEN) v0 = *(const float4*)(xb + (size_t)g * CIN + c4 * 4);
            else { v0 = make_float4(0.f, 0.f, 0.f, 0.f); if (c4 == 0) v0.x = 1.0f; }
            if ((unsigned)(g + 1) < (unsigned)LLEN) v1 = *(const float4*)(xb + (size_t)(g + 1) * CIN + c4 * 4);
            else { v1 = make_float4(0.f, 0.f, 0.f, 0.f); if (c4 == 0) v1.x = 1.0f; }
            uint4 pw;
            pw.x = h2pack(v0.x, v1.x); pw.y = h2pack(v0.y, v1.y);
            pw.z = h2pack(v0.z, v1.z); pw.w = h2pack(v0.w, v1.w);
            *(uint4*)(sm + wpbase + r * XPS + c4 * 4) = pw;
        }
    }
    __syncwarp();

    // ---- mainloop: warp tile 32 rows x 64 cols, 24 k-blocks ----
    const int q4 = lane >> 2;
    const int s4 = lane & 3;
    const int bx = wpbase + q4 * XPS + 2 * s4;   // A base (word index)
    const int ub = (q4 * 4 + s4) * LGSTR;        // B base (uint4 index)

    float d[2][8][4];
#pragma unroll
    for (int m = 0; m < 2; m++)
#pragma unroll
        for (int nb = 0; nb < 8; nb++)
            d[m][nb][0] = d[m][nb][1] = d[m][nb][2] = d[m][nb][3] = 0.f;

#pragma unroll
    for (int kb = 0; kb < 24; kb++) {
        const int kk = 2 * (kb % 3);
        const int cb = 8 * (kb / 3);

        uint4 b0 = BQ4[ub + kb * 4 + 0];
        uint4 b1 = BQ4[ub + kb * 4 + 1];
        uint4 b2 = BQ4[ub + kb * 4 + 2];
        uint4 b3 = BQ4[ub + kb * 4 + 3];

#pragma unroll
        for (int m = 0; m < 2; m++) {
            uint2 lo = *(const uint2*)(sm + bx + (kk + 16 * m) * XPS + cb);      // {a0, a2}
            uint2 hi = *(const uint2*)(sm + bx + (kk + 16 * m + 8) * XPS + cb);  // {a1, a3}
            mma_f16(d[m][0], lo.x, hi.x, lo.y, hi.y, b0.x, b0.y);
            mma_f16(d[m][1], lo.x, hi.x, lo.y, hi.y, b0.z, b0.w);
            mma_f16(d[m][2], lo.x, hi.x, lo.y, hi.y, b1.x, b1.y);
            mma_f16(d[m][3], lo.x, hi.x, lo.y, hi.y, b1.z, b1.w);
            mma_f16(d[m][4], lo.x, hi.x, lo.y, hi.y, b2.x, b2.y);
            mma_f16(d[m][5], lo.x, hi.x, lo.y, hi.y, b2.z, b2.w);
            mma_f16(d[m][6], lo.x, hi.x, lo.y, hi.y, b3.x, b3.y);
            mma_f16(d[m][7], lo.x, hi.x, lo.y, hi.y, b3.z, b3.w);
        }
    }

    // ---- epilogue: + W[:,0]*t_resc + b, Lorentz norm (in-warp over s4), store ----
#pragma unroll
    for (int m = 0; m < 2; m++) {
        const int ra = wrow + 16 * m + q4;
        const float tra = tresc(xb, l0 + ra);
        const float trb = tresc(xb, l0 + ra + 8);
        float ssa = 0.f, ssb = 0.f;
#pragma unroll
        for (int nb = 0; nb < 8; nb++) {
            float4 f4 = wb4[nb * 4 + s4];
            float y0 = fmaf(f4.x, tra, d[m][nb][0]) + f4.y;
            float y1 = fmaf(f4.z, tra, d[m][nb][1]) + f4.w;
            float y2 = fmaf(f4.x, trb, d[m][nb][2]) + f4.y;
            float y3 = fmaf(f4.z, trb, d[m][nb][3]) + f4.w;
            if (!(nb == 0 && s4 == 0)) {       // global col 0 excluded from the norm
                ssa = fmaf(y0, y0, ssa);
                ssb = fmaf(y2, y2, ssb);
            }
            ssa = fmaf(y1, y1, ssa);
            ssb = fmaf(y3, y3, ssb);
            d[m][nb][0] = y0; d[m][nb][1] = y1;
            d[m][nb][2] = y2; d[m][nb][3] = y3;
        }
        ssa += __shfl_xor_sync(0xffffffffu, ssa, 1);
        ssa += __shfl_xor_sync(0xffffffffu, ssa, 2);
        ssb += __shfl_xor_sync(0xffffffffu, ssb, 1);
        ssb += __shfl_xor_sync(0xffffffffu, ssb, 2);
        if (s4 == 0) {
            d[m][0][0] = sqrtf(ssa + 1.0f);
            d[m][0][2] = sqrtf(ssb + 1.0f);
        }

        const size_t oa = ((size_t)bidx * LLEN + (size_t)(l0 + ra)) * 64 + 2 * s4;
        const size_t ob = oa + 8 * 64;
#pragma unroll
        for (int nb = 0; nb < 8; nb++) {
            *(float2*)(out + oa + nb * 8) = make_float2(d[m][nb][0], d[m][nb][1]);
            *(float2*)(out + ob + nb * 8) = make_float2(d[m][nb][2], d[m][nb][3]);
        }
    }
}

extern "C" void kernel_launch(void* const* d_in, const int* in_sizes, int n_in,
                              void* d_out, int out_size)
{
    const float* x = (const float*)d_in[0];
    const float* W = (const float*)d_in[1];
    const float* b = (const float*)d_in[2];
    float* out = (float*)d_out;

    cudaFuncSetAttribute(lorentz_f16_kernel,
                         cudaFuncAttributeMaxDynamicSharedMemorySize, SMEM_BYTES);
    lorentz_f16_kernel<<<256, 512, SMEM_BYTES>>>(x, W, b, out);
}

// round 10
// speedup vs baseline: 1.1719x; 1.1719x over previous
#include <cuda_runtime.h>
#include <cuda_fp16.h>
#include <cstdint>

// LorentzConv1d via single-pass fp16 mma.sync m16n8k16 (fp32 accum).
// Warp tile 32x64, 16 warps, MT=512 rows/CTA, grid=256. Warp-private A staging.
//
// Round 10 K-permutation (K=320, 20 kb x 8 pair-slots), row-major pairing:
//   kb = 4*kIdx + jg, kIdx(tap) 0..4, jg 0..3
//   pair w (0..7) of kb = (tap kIdx, channels 16jg+2w, 16jg+2w+1)
//   channel 0 (time) slots multiply B=0 (t_resc handled in fp32 epilogue).
// A tile xq = plain row-major fp16: word c holds channels {2c, 2c+1}.
//   a0 = xq[q4+kIdx+16m][8jg+s4], a1 = +8 rows, a2 = word+4, a3 = both.
//   XQS=36 -> word bank = 4*q4 + s4 + const: conflict-free across full warp.

#define LLEN 8192
#define CIN  64
#define MT   512
#define XQS  36
#define WPRIV (36 * XQS)              // 1296 words per warp
#define WB4_OFF (16 * WPRIV)          // 20736 (16B aligned)
#define B_OFF   (WB4_OFF + 128)       // 20864 (16B aligned)
#define LGSTR   81                    // uint4 units per lane slot (20*4 + 1, odd)
#define B_UNITS (32 * LGSTR)          // 2592
#define SMEM_WORDS (B_OFF + B_UNITS * 4)  // 31232
#define SMEM_BYTES (SMEM_WORDS * 4)       // 124928

__device__ __forceinline__ uint32_t h2pack(float a, float b) {
    __half2 h = __floats2half2_rn(a, b);
    return *(uint32_t*)&h;
}
__device__ __forceinline__ void mma_f16(float* d, uint32_t a0, uint32_t a1,
                                        uint32_t a2, uint32_t a3,
                                        uint32_t b0, uint32_t b1) {
    asm volatile(
        "mma.sync.aligned.m16n8k16.row.col.f32.f16.f16.f32 "
        "{%0,%1,%2,%3}, {%4,%5,%6,%7}, {%8,%9}, {%0,%1,%2,%3};"
        : "+f"(d[0]), "+f"(d[1]), "+f"(d[2]), "+f"(d[3])
        : "r"(a0), "r"(a1), "r"(a2), "r"(a3), "r"(b0), "r"(b1));
}
// W weight for (kb, pair w, elem t): tap kIdx = kb>>2, channel 16*(kb&3)+2w+t
__device__ __forceinline__ float slotW(const float* __restrict__ W, int n,
                                       int kb, int w, int t) {
    int kIdx = kb >> 2;
    int jg   = kb & 3;
    int ch   = 16 * jg + 2 * w + t;
    if (ch == 0) return 0.f;          // time channel: zero in GEMM
    return W[(size_t)n * 316 + (ch - 1) * 5 + kIdx + 1];
}
__device__ __forceinline__ float tresc(const float* __restrict__ xb, int l) {
    float s = -4.0f;
#pragma unroll
    for (int k = 0; k < 5; k++) {
        int g = l - 2 + k;
        float t = ((unsigned)g < (unsigned)LLEN) ? xb[(size_t)g * CIN] : 1.0f;
        s = fmaf(t, t, s);
    }
    return sqrtf(s);
}

__global__ __launch_bounds__(512, 1)
void lorentz_f16_kernel(const float* __restrict__ x,
                        const float* __restrict__ W,
                        const float* __restrict__ bvec,
                        float* __restrict__ out)
{
    extern __shared__ uint32_t sm[];
    float4* wb4 = (float4*)(sm + WB4_OFF);
    uint4*  BQ4 = (uint4*)(sm + B_OFF);

    const int tid  = threadIdx.x;
    const int wid  = tid >> 5;
    const int lane = tid & 31;
    const int bidx = blockIdx.x >> 4;          // 16 tiles per batch
    const int l0   = (blockIdx.x & 15) << 9;   // 512 rows per tile
    const float* xb = x + (size_t)bidx * (LLEN * CIN);

    // ---- stage B (CTA-shared): unit (lg, kb, i) holds n = 16i+q4g and 16i+8+q4g ----
    for (int u = tid; u < 32 * 20 * 4; u += 512) {
        int i  = u & 3;
        int t2 = u >> 2;
        int kb = t2 % 20;
        int lg = t2 / 20;                      // 0..31
        int q4g = lg >> 2, s4g = lg & 3;
        int n0 = 16 * i + q4g;
        int n1 = n0 + 8;
        uint4 w;
        w.x = h2pack(slotW(W, n0, kb, s4g, 0),     slotW(W, n0, kb, s4g, 1));
        w.y = h2pack(slotW(W, n0, kb, s4g + 4, 0), slotW(W, n0, kb, s4g + 4, 1));
        w.z = h2pack(slotW(W, n1, kb, s4g, 0),     slotW(W, n1, kb, s4g, 1));
        w.w = h2pack(slotW(W, n1, kb, s4g + 4, 0), slotW(W, n1, kb, s4g + 4, 1));
        BQ4[lg * LGSTR + kb * 4 + i] = w;
    }
    // ---- fp32 time-weight + bias pairs ----
    if (tid < 32) {
        wb4[tid] = make_float4(W[(size_t)(2 * tid) * 316], bvec[2 * tid],
                               W[(size_t)(2 * tid + 1) * 316], bvec[2 * tid + 1]);
    }
    __syncthreads();   // the ONLY CTA-wide barrier

    // ---- warp-private xq staging: 36 rows, row-major fp16 ----
    const int wrow   = wid * 32;
    const int wpbase = wid * WPRIV;
    {
        const int gbase = l0 + wrow - 2;
#pragma unroll
        for (int j = 0; j < 18; j++) {
            int u  = j * 32 + lane;
            int r  = u >> 4, c4 = u & 15;
            int g  = gbase + r;
            float4 v;
            if ((unsigned)g < (unsigned)LLEN) v = *(const float4*)(xb + (size_t)g * CIN + c4 * 4);
            else { v = make_float4(0.f, 0.f, 0.f, 0.f); if (c4 == 0) v.x = 1.0f; }
            uint2 pw;
            pw.x = h2pack(v.x, v.y);
            pw.y = h2pack(v.z, v.w);
            *(uint2*)(sm + wpbase + r * XQS + c4 * 2) = pw;
        }
    }
    __syncwarp();

    // ---- mainloop: warp tile 32 rows x 64 cols, 20 k-blocks ----
    const int q4 = lane >> 2;
    const int s4 = lane & 3;
    const int bx = wpbase + q4 * XQS + s4;     // A base (word index)
    const int ub = (q4 * 4 + s4) * LGSTR;      // B base (uint4 index)

    float d[2][8][4];
#pragma unroll
    for (int m = 0; m < 2; m++)
#pragma unroll
        for (int nb = 0; nb < 8; nb++)
            d[m][nb][0] = d[m][nb][1] = d[m][nb][2] = d[m][nb][3] = 0.f;

#pragma unroll
    for (int kb = 0; kb < 20; kb++) {
        const int kIdx = kb >> 2;
        const int jg   = kb & 3;
        const int boff = kIdx * XQS + 8 * jg;  // row tap + word-group offset

        uint4 b0 = BQ4[ub + kb * 4 + 0];
        uint4 b1 = BQ4[ub + kb * 4 + 1];
        uint4 b2 = BQ4[ub + kb * 4 + 2];
        uint4 b3 = BQ4[ub + kb * 4 + 3];

#pragma unroll
        for (int m = 0; m < 2; m++) {
            const int base0 = bx + boff + (16 * m) * XQS;
            const int base1 = base0 + 8 * XQS;
            uint32_t a0 = sm[base0];
            uint32_t a1 = sm[base1];
            uint32_t a2 = sm[base0 + 4];
            uint32_t a3 = sm[base1 + 4];
            mma_f16(d[m][0], a0, a1, a2, a3, b0.x, b0.y);
            mma_f16(d[m][1], a0, a1, a2, a3, b0.z, b0.w);
            mma_f16(d[m][2], a0, a1, a2, a3, b1.x, b1.y);
            mma_f16(d[m][3], a0, a1, a2, a3, b1.z, b1.w);
            mma_f16(d[m][4], a0, a1, a2, a3, b2.x, b2.y);
            mma_f16(d[m][5], a0, a1, a2, a3, b2.z, b2.w);
            mma_f16(d[m][6], a0, a1, a2, a3, b3.x, b3.y);
            mma_f16(d[m][7], a0, a1, a2, a3, b3.z, b3.w);
        }
    }

    // ---- epilogue: + W[:,0]*t_resc + b, Lorentz norm (in-warp over s4), store ----
#pragma unroll
    for (int m = 0; m < 2; m++) {
        const int ra = wrow + 16 * m + q4;
        const float tra = tresc(xb, l0 + ra);
        const float trb = tresc(xb, l0 + ra + 8);
        float ssa = 0.f, ssb = 0.f;
#pragma unroll
        for (int nb = 0; nb < 8; nb++) {
            float4 f4 = wb4[nb * 4 + s4];
            float y0 = fmaf(f4.x, tra, d[m][nb][0]) + f4.y;
            float y1 = fmaf(f4.z, tra, d[m][nb][1]) + f4.w;
            float y2 = fmaf(f4.x, trb, d[m][nb][2]) + f4.y;
            float y3 = fmaf(f4.z, trb, d[m][nb][3]) + f4.w;
            if (!(nb == 0 && s4 == 0)) {       // global col 0 excluded from the norm
                ssa = fmaf(y0, y0, ssa);
                ssb = fmaf(y2, y2, ssb);
            }
            ssa = fmaf(y1, y1, ssa);
            ssb = fmaf(y3, y3, ssb);
            d[m][nb][0] = y0; d[m][nb][1] = y1;
            d[m][nb][2] = y2; d[m][nb][3] = y3;
        }
        ssa += __shfl_xor_sync(0xffffffffu, ssa, 1);
        ssa += __shfl_xor_sync(0xffffffffu, ssa, 2);
        ssb += __shfl_xor_sync(0xffffffffu, ssb, 1);
        ssb += __shfl_xor_sync(0xffffffffu, ssb, 2);
        if (s4 == 0) {
            d[m][0][0] = sqrtf(ssa + 1.0f);
            d[m][0][2] = sqrtf(ssb + 1.0f);
        }

        const size_t oa = ((size_t)bidx * LLEN + (size_t)(l0 + ra)) * 64 + 2 * s4;
        const size_t ob = oa + 8 * 64;
#pragma unroll
        for (int nb = 0; nb < 8; nb++) {
            *(float2*)(out + oa + nb * 8) = make_float2(d[m][nb][0], d[m][nb][1]);
            *(float2*)(out + ob + nb * 8) = make_float2(d[m][nb][2], d[m][nb][3]);
        }
    }
}

extern "C" void kernel_launch(void* const* d_in, const int* in_sizes, int n_in,
                              void* d_out, int out_size)
{
    const float* x = (const float*)d_in[0];
    const float* W = (const float*)d_in[1];
    const float* b = (const float*)d_in[2];
    float* out = (float*)d_out;

    cudaFuncSetAttribute(lorentz_f16_kernel,
                         cudaFuncAttributeMaxDynamicSharedMemorySize, SMEM_BYTES);
    lorentz_f16_kernel<<<256, 512, SMEM_BYTES>>>(x, W, b, out);
}